// round 1
// baseline (speedup 1.0000x reference)
#include <cuda_runtime.h>
#include <cstdint>
#include <cstddef>

// ============================================================================
// MultiHeadAttention (per-token head-axis attention) for GB300
//   Y[16384,3072] = x @ [Wq;Wk;Wv]^T      (TF32 tensor-core GEMM)
//   per-token: softmax(Q Kt / 8) V        (one warp per token)
//   out       = O @ Wfc^T                 (TF32 tensor-core GEMM)
// ============================================================================

#define BM 128
#define BN 128
#define BK 16
#define KS 20          // BK + 4 pad (frag loads conflict-free: bank = 4r+c)
#define NTHREADS 256

// Scratch (allocation-free rule: __device__ globals)
__device__ float g_Y[50331648];   // 16384 x 3072
__device__ float g_O[16777216];   // 16384 x 1024

__device__ __forceinline__ uint32_t f2tf32(float x) {
    uint32_t u;
    asm("cvt.rna.tf32.f32 %0, %1;" : "=r"(u) : "f"(x));
    return u;
}

__device__ __forceinline__ void cp16(uint32_t saddr, const void* gptr) {
    asm volatile("cp.async.cg.shared.global [%0], [%1], 16;\n"
                 :: "r"(saddr), "l"(gptr));
}
__device__ __forceinline__ void cp_commit() {
    asm volatile("cp.async.commit_group;\n");
}
__device__ __forceinline__ void cp_wait0() {
    asm volatile("cp.async.wait_group 0;\n");
}

__device__ __forceinline__ void mma_tf32(float c[4], const uint32_t a[4], const uint32_t b[2]) {
    asm volatile(
        "mma.sync.aligned.m16n8k8.row.col.f32.tf32.tf32.f32 "
        "{%0,%1,%2,%3}, {%4,%5,%6,%7}, {%8,%9}, {%0,%1,%2,%3};\n"
        : "+f"(c[0]), "+f"(c[1]), "+f"(c[2]), "+f"(c[3])
        : "r"(a[0]), "r"(a[1]), "r"(a[2]), "r"(a[3]),
          "r"(b[0]), "r"(b[1]));
}

// C[M, ldc] tile (blockIdx.y -> 128 rows of A, blockIdx.x -> 128 cols of C)
//   = A[M,K] @ Bsel[N,K]^T, Bsel picked per 1024-column group (Wq/Wk/Wv stack).
__global__ void __launch_bounds__(NTHREADS)
gemm_tf32_nt(const float* __restrict__ A,
             const float* __restrict__ B0,
             const float* __restrict__ B1,
             const float* __restrict__ B2,
             float* __restrict__ C, int ldc, int K)
{
    __shared__ float As[2][BM * KS];
    __shared__ float Bs[2][BN * KS];

    const int tid  = threadIdx.x;
    const int lane = tid & 31;
    const int wid  = tid >> 5;
    const int warp_m = wid & 1;    // 2 warps along M (64 rows each)
    const int warp_n = wid >> 1;   // 4 warps along N (32 cols each)

    const int mtile = blockIdx.y;
    const int wsel  = blockIdx.x >> 3;                     // which weight matrix
    const float* B  = (wsel == 0) ? B0 : (wsel == 1 ? B1 : B2);
    const int nbase_local  = (blockIdx.x & 7) * BN;        // row within B
    const int nbase_global = blockIdx.x * BN;              // col within C

    const float* Ab = A + (size_t)(mtile * BM) * K;
    const float* Bb = B + (size_t)nbase_local * K;

    const uint32_t as_base = (uint32_t)__cvta_generic_to_shared(&As[0][0]);
    const uint32_t bs_base = (uint32_t)__cvta_generic_to_shared(&Bs[0][0]);

    // per-thread load slots: 512 float4 per tile per operand, 2 each
    auto load_tile = [&](int kt, int stage) {
        const float* ag = Ab + kt * BK;
        const float* bg = Bb + kt * BK;
#pragma unroll
        for (int i = 0; i < 2; i++) {
            int f  = tid + i * 256;     // float4 index 0..511
            int r  = f >> 2;            // row 0..127
            int c4 = f & 3;             // which float4 in the 16-float row
            uint32_t so = (uint32_t)((stage * BM * KS + r * KS + c4 * 4) * 4);
            cp16(as_base + so, ag + (size_t)r * K + c4 * 4);
            cp16(bs_base + so, bg + (size_t)r * K + c4 * 4);
        }
    };

    float acc[4][4][4];
#pragma unroll
    for (int mt = 0; mt < 4; mt++)
#pragma unroll
        for (int nt = 0; nt < 4; nt++)
#pragma unroll
            for (int i = 0; i < 4; i++) acc[mt][nt][i] = 0.f;

    const int NKT = K >> 4;   // K / BK

    load_tile(0, 0);
    cp_commit();
    cp_wait0();
    __syncthreads();

    for (int kt = 0; kt < NKT; kt++) {
        const int cur = kt & 1;
        if (kt + 1 < NKT) {
            load_tile(kt + 1, cur ^ 1);
            cp_commit();
        }

        const float* Ass = &As[cur][0];
        const float* Bss = &Bs[cur][0];

#pragma unroll
        for (int ks = 0; ks < 2; ks++) {
            const int k0 = ks * 8;
            uint32_t a[4][4];
            uint32_t b[4][2];
#pragma unroll
            for (int mt = 0; mt < 4; mt++) {
                const int r  = warp_m * 64 + mt * 16 + (lane >> 2);
                const int cc = k0 + (lane & 3);
                a[mt][0] = f2tf32(Ass[r * KS + cc]);
                a[mt][1] = f2tf32(Ass[(r + 8) * KS + cc]);
                a[mt][2] = f2tf32(Ass[r * KS + cc + 4]);
                a[mt][3] = f2tf32(Ass[(r + 8) * KS + cc + 4]);
            }
#pragma unroll
            for (int nt = 0; nt < 4; nt++) {
                const int r  = warp_n * 32 + nt * 8 + (lane >> 2);
                const int cc = k0 + (lane & 3);
                b[nt][0] = f2tf32(Bss[r * KS + cc]);
                b[nt][1] = f2tf32(Bss[r * KS + cc + 4]);
            }
#pragma unroll
            for (int mt = 0; mt < 4; mt++)
#pragma unroll
                for (int nt = 0; nt < 4; nt++)
                    mma_tf32(acc[mt][nt], a[mt], b[nt]);
        }

        cp_wait0();
        __syncthreads();
    }

    // epilogue
    float* Cb = C + (size_t)(mtile * BM) * ldc + nbase_global;
#pragma unroll
    for (int mt = 0; mt < 4; mt++) {
#pragma unroll
        for (int nt = 0; nt < 4; nt++) {
            const int r0 = warp_m * 64 + mt * 16 + (lane >> 2);
            const int c0 = warp_n * 32 + nt * 8 + 2 * (lane & 3);
            float2 v01 = make_float2(acc[mt][nt][0], acc[mt][nt][1]);
            float2 v23 = make_float2(acc[mt][nt][2], acc[mt][nt][3]);
            *(float2*)(Cb + (size_t)r0 * ldc + c0)       = v01;
            *(float2*)(Cb + (size_t)(r0 + 8) * ldc + c0) = v23;
        }
    }
}

// ============================================================================
// Per-token head-axis attention: one warp per token, 2 tokens per 64-thr block
//   Q,K,V = Y[m, 0:1024 / 1024:2048 / 2048:3072] viewed as [16,64]
//   O[m, h*64+d] = sum_t softmax_t(Q[h]·K[t]/8) * V[t,d]
// ============================================================================
#define QKV_LD 68   // 64 + 4 pad
__global__ void __launch_bounds__(64)
attn_kernel(const float* __restrict__ Y, float* __restrict__ O)
{
    __shared__ float sm[2][3 * 16 * QKV_LD + 16 * 17];

    const int lane = threadIdx.x & 31;
    const int w    = threadIdx.x >> 5;
    const int m    = blockIdx.x * 2 + w;

    float* q  = &sm[w][0];
    float* k  = q + 16 * QKV_LD;
    float* v  = k + 16 * QKV_LD;
    float* sc = v + 16 * QKV_LD;

    const float* src = Y + (size_t)m * 3072;

    // stage QKV: 768 float4 per token
#pragma unroll
    for (int it = 0; it < 24; it++) {
        const int f = it * 32 + lane;            // 0..767
        float4 val  = ((const float4*)src)[f];
        const int sec  = f >> 8;                 // 0=Q 1=K 2=V
        const int wi   = f & 255;
        const int row  = wi >> 4;                // 16 float4 per 64-float row
        const int col4 = wi & 15;
        float* dst = (sec == 0) ? q : (sec == 1 ? k : v);
        *(float4*)(dst + row * QKV_LD + col4 * 4) = val;
    }
    __syncwarp();

    // scores[h][t] = Q[h]·K[t] / 8
#pragma unroll
    for (int p = 0; p < 8; p++) {
        const int idx = p * 32 + lane;
        const int h = idx >> 4, t = idx & 15;
        float s = 0.f;
#pragma unroll
        for (int d4 = 0; d4 < 16; d4++) {
            float4 qv = *(const float4*)(q + h * QKV_LD + d4 * 4);
            float4 kv = *(const float4*)(k + t * QKV_LD + d4 * 4);
            s += qv.x * kv.x + qv.y * kv.y + qv.z * kv.z + qv.w * kv.w;
        }
        sc[h * 17 + t] = s * 0.125f;
    }
    __syncwarp();

    // softmax over t, one head per lane
    if (lane < 16) {
        float mx = -1e30f;
#pragma unroll
        for (int t = 0; t < 16; t++) mx = fmaxf(mx, sc[lane * 17 + t]);
        float sum = 0.f;
#pragma unroll
        for (int t = 0; t < 16; t++) {
            float e = __expf(sc[lane * 17 + t] - mx);
            sum += e;
            sc[lane * 17 + t] = e;
        }
        const float inv = 1.f / sum;
#pragma unroll
        for (int t = 0; t < 16; t++) sc[lane * 17 + t] *= inv;
    }
    __syncwarp();

    // O[h][d] = sum_t attn[h][t] V[t][d]
    float* dst = O + (size_t)m * 1024;
#pragma unroll
    for (int i = 0; i < 32; i++) {
        const int idx = i * 32 + lane;           // 0..1023
        const int h = idx >> 6, d = idx & 63;
        float a0 = 0.f;
#pragma unroll
        for (int t = 0; t < 16; t++) a0 += sc[h * 17 + t] * v[t * QKV_LD + d];
        dst[idx] = a0;
    }
}

// ============================================================================
extern "C" void kernel_launch(void* const* d_in, const int* in_sizes, int n_in,
                              void* d_out, int out_size)
{
    (void)in_sizes; (void)n_in; (void)out_size;
    const float* x   = (const float*)d_in[0];
    const float* Wq  = (const float*)d_in[1];
    const float* Wk  = (const float*)d_in[2];
    const float* Wv  = (const float*)d_in[3];
    const float* Wfc = (const float*)d_in[4];
    float* out = (float*)d_out;

    float *Yp = nullptr, *Op = nullptr;
    cudaGetSymbolAddress((void**)&Yp, g_Y);
    cudaGetSymbolAddress((void**)&Op, g_O);

    // GEMM1: Y = x @ [Wq;Wk;Wv]^T    (16384 x 3072, K=1024)
    gemm_tf32_nt<<<dim3(24, 128), NTHREADS>>>(x, Wq, Wk, Wv, Yp, 3072, 1024);
    // per-token attention: 2 tokens per block
    attn_kernel<<<8192, 64>>>(Yp, Op);
    // GEMM2: out = O @ Wfc^T         (16384 x 1024, K=1024)
    gemm_tf32_nt<<<dim3(8, 128), NTHREADS>>>(Op, Wfc, Wfc, Wfc, out, 1024, 1024);
}

// round 3
// speedup vs baseline: 1.0092x; 1.0092x over previous
#include <cuda_runtime.h>
#include <cstdint>
#include <cstddef>

// ============================================================================
// MultiHeadAttention (per-token head-axis attention) on GB300
// Legacy mma.sync TF32 path (tcgen05 PTX rejected at compute_103 virtual arch).
//   prologue: round x, Wq|Wk|Wv|Wfc to tf32 (rna) -> no cvt in GEMM inner loop
//   GEMM1: Y[16384,3072] = xr @ Wqkv^T   (CTA 128x256, warp 64x64)
//   attn : per-token 16x16 head attention, O stored tf32-rounded
//   GEMM2: out = O @ Wfc^T
// ============================================================================

#define BM 128
#define BN 256
#define BK 16
#define KS 20            // BK + 4 pad -> conflict-free frag LDS
#define NTHREADS 256

// dynamic smem layout (bytes):
//   As[2] : stage s at      s*10240   (128 rows * 20 floats)
//   Bs[2] : stage s at 20480 + s*20480 (256 rows * 20 floats)
#define AS_STAGE_B 10240
#define BS_BASE_B  20480
#define BS_STAGE_B 20480
#define SMEM_TOTAL (BS_BASE_B + 2 * BS_STAGE_B)   // 61440

__device__ float g_Y[50331648];   // 16384 x 3072
__device__ float g_O[16777216];   // 16384 x 1024
__device__ float g_Xr[16777216];  // x rounded to tf32
__device__ float g_W[4194304];    // Wq|Wk|Wv|Wfc rounded to tf32

__device__ __forceinline__ uint32_t f2tf32(float x) {
    uint32_t u;
    asm("cvt.rna.tf32.f32 %0, %1;" : "=r"(u) : "f"(x));
    return u;
}
__device__ __forceinline__ void cp16(uint32_t saddr, const void* gptr) {
    asm volatile("cp.async.cg.shared.global [%0], [%1], 16;\n" :: "r"(saddr), "l"(gptr));
}
__device__ __forceinline__ void cp_commit() { asm volatile("cp.async.commit_group;\n"); }
__device__ __forceinline__ void cp_wait0()  { asm volatile("cp.async.wait_group 0;\n"); }

__device__ __forceinline__ void mma_tf32(float c[4], const uint32_t a[4], const uint32_t b[2]) {
    asm volatile(
        "mma.sync.aligned.m16n8k8.row.col.f32.tf32.tf32.f32 "
        "{%0,%1,%2,%3}, {%4,%5,%6,%7}, {%8,%9}, {%0,%1,%2,%3};\n"
        : "+f"(c[0]), "+f"(c[1]), "+f"(c[2]), "+f"(c[3])
        : "r"(a[0]), "r"(a[1]), "r"(a[2]), "r"(a[3]),
          "r"(b[0]), "r"(b[1]));
}

// ============================================================================
// TF32 GEMM: C[128x256 tile] = A[M,K] @ B[N,K]^T  (A,B pre-rounded to tf32)
// 8 warps, warp tile 64x64 (warp_m = wid&1, warp_n = wid>>1)
// ============================================================================
__global__ void __launch_bounds__(NTHREADS, 1)
gemm_tf32_nt(const float* __restrict__ A, const float* __restrict__ B,
             float* __restrict__ C, int ldc, int K)
{
    extern __shared__ __align__(128) char smem[];
    uint32_t* s32 = (uint32_t*)smem;

    const int tid  = threadIdx.x;
    const int lane = tid & 31;
    const int wid  = tid >> 5;
    const int warp_m = wid & 1;     // 2 warps along M (64 rows)
    const int warp_n = wid >> 1;    // 4 warps along N (64 cols)

    const int mtile = blockIdx.y;
    const int ntile = blockIdx.x;

    const float* Ab = A + (size_t)(mtile * BM) * K;
    const float* Bb = B + (size_t)(ntile * BN) * K;

    uint32_t smem_base;
    asm("{ .reg .u64 t; cvta.to.shared.u64 t, %1; cvt.u32.u64 %0, t; }"
        : "=r"(smem_base) : "l"(smem));

    // ---- tile loader: A 512 float4 (2/thread), B 1024 float4 (4/thread)
    auto load_tile = [&](int kt, int stage) {
        const float* ag = Ab + kt * BK;
        const float* bg = Bb + kt * BK;
        const uint32_t a0 = smem_base + stage * AS_STAGE_B;
        const uint32_t b0 = smem_base + BS_BASE_B + stage * BS_STAGE_B;
#pragma unroll
        for (int i = 0; i < 2; i++) {
            int f  = tid + i * 256;       // 0..511
            int r  = f >> 2;
            int c4 = f & 3;
            cp16(a0 + (uint32_t)(r * KS + c4 * 4) * 4, ag + (size_t)r * K + c4 * 4);
        }
#pragma unroll
        for (int i = 0; i < 4; i++) {
            int f  = tid + i * 256;       // 0..1023
            int r  = f >> 2;
            int c4 = f & 3;
            cp16(b0 + (uint32_t)(r * KS + c4 * 4) * 4, bg + (size_t)r * K + c4 * 4);
        }
    };

    float acc[4][8][4];
#pragma unroll
    for (int mt = 0; mt < 4; mt++)
#pragma unroll
        for (int nt = 0; nt < 8; nt++)
#pragma unroll
            for (int i = 0; i < 4; i++) acc[mt][nt][i] = 0.f;

    const int NKT = K >> 4;

    load_tile(0, 0);
    cp_commit();
    cp_wait0();
    __syncthreads();

    const int ar_base = warp_m * 64 + (lane >> 2);   // A row within tile
    const int br_base = warp_n * 64 + (lane >> 2);   // B row (C col) within tile
    const int kc      = lane & 3;

    for (int kt = 0; kt < NKT; kt++) {
        const int cur = kt & 1;
        if (kt + 1 < NKT) {
            load_tile(kt + 1, cur ^ 1);
            cp_commit();
        }

        const uint32_t* Ass = s32 + (cur * AS_STAGE_B) / 4;
        const uint32_t* Bss = s32 + (BS_BASE_B + cur * BS_STAGE_B) / 4;

#pragma unroll
        for (int ks = 0; ks < 2; ks++) {
            const int cc = ks * 8 + kc;
            uint32_t a[4][4];
            uint32_t b[8][2];
#pragma unroll
            for (int mt = 0; mt < 4; mt++) {
                const int r = ar_base + mt * 16;
                a[mt][0] = Ass[r * KS + cc];
                a[mt][1] = Ass[(r + 8) * KS + cc];
                a[mt][2] = Ass[r * KS + cc + 4];
                a[mt][3] = Ass[(r + 8) * KS + cc + 4];
            }
#pragma unroll
            for (int nt = 0; nt < 8; nt++) {
                const int r = br_base + nt * 8;
                b[nt][0] = Bss[r * KS + cc];
                b[nt][1] = Bss[r * KS + cc + 4];
            }
#pragma unroll
            for (int mt = 0; mt < 4; mt++)
#pragma unroll
                for (int nt = 0; nt < 8; nt++)
                    mma_tf32(acc[mt][nt], a[mt], b[nt]);
        }

        cp_wait0();
        __syncthreads();
    }

    // ---- epilogue
    float* Cb = C + (size_t)(mtile * BM) * ldc + (size_t)ntile * BN;
#pragma unroll
    for (int mt = 0; mt < 4; mt++) {
#pragma unroll
        for (int nt = 0; nt < 8; nt++) {
            const int r0 = warp_m * 64 + mt * 16 + (lane >> 2);
            const int c0 = warp_n * 64 + nt * 8 + 2 * (lane & 3);
            *(float2*)(Cb + (size_t)r0 * ldc + c0) =
                make_float2(acc[mt][nt][0], acc[mt][nt][1]);
            *(float2*)(Cb + (size_t)(r0 + 8) * ldc + c0) =
                make_float2(acc[mt][nt][2], acc[mt][nt][3]);
        }
    }
}

// ============================================================================
// Prologue: round fp32 -> tf32 (rna)
// ============================================================================
__global__ void __launch_bounds__(256)
round_tf32(const float4* __restrict__ src, float4* __restrict__ dst, int n4)
{
    int i = blockIdx.x * 256 + threadIdx.x;
    if (i < n4) {
        float4 v = src[i];
        v.x = __uint_as_float(f2tf32(v.x));
        v.y = __uint_as_float(f2tf32(v.y));
        v.z = __uint_as_float(f2tf32(v.z));
        v.w = __uint_as_float(f2tf32(v.w));
        dst[i] = v;
    }
}

// all four weight matrices in one launch: blockIdx.x selects 1024-block chunk
__global__ void __launch_bounds__(256)
round_w(const float4* __restrict__ w0, const float4* __restrict__ w1,
        const float4* __restrict__ w2, const float4* __restrict__ w3,
        float4* __restrict__ dst)
{
    int bx = blockIdx.x;                 // 0..4095
    int m  = bx >> 10;                   // which matrix
    int i  = (bx & 1023) * 256 + threadIdx.x;   // 0..262143
    const float4* src = (m == 0) ? w0 : (m == 1) ? w1 : (m == 2) ? w2 : w3;
    float4 v = src[i];
    v.x = __uint_as_float(f2tf32(v.x));
    v.y = __uint_as_float(f2tf32(v.y));
    v.z = __uint_as_float(f2tf32(v.z));
    v.w = __uint_as_float(f2tf32(v.w));
    dst[(size_t)m * 262144 + i] = v;
}

// ============================================================================
// Per-token head-axis attention: one warp per token, 2 tokens per block.
// O stored tf32-rounded (feeds GEMM2's A operand).
// ============================================================================
#define QKV_LD 68
__global__ void __launch_bounds__(64)
attn_kernel(const float* __restrict__ Y, float* __restrict__ O)
{
    __shared__ float sm[2][3 * 16 * QKV_LD + 16 * 17];

    const int lane = threadIdx.x & 31;
    const int w    = threadIdx.x >> 5;
    const int m    = blockIdx.x * 2 + w;

    float* q  = &sm[w][0];
    float* k  = q + 16 * QKV_LD;
    float* v  = k + 16 * QKV_LD;
    float* sc = v + 16 * QKV_LD;

    const float* src = Y + (size_t)m * 3072;

#pragma unroll
    for (int it = 0; it < 24; it++) {
        const int f = it * 32 + lane;
        float4 val  = ((const float4*)src)[f];
        const int sec  = f >> 8;
        const int wi   = f & 255;
        const int row  = wi >> 4;
        const int col4 = wi & 15;
        float* dst = (sec == 0) ? q : (sec == 1 ? k : v);
        *(float4*)(dst + row * QKV_LD + col4 * 4) = val;
    }
    __syncwarp();

#pragma unroll
    for (int p = 0; p < 8; p++) {
        const int idx = p * 32 + lane;
        const int h = idx >> 4, t = idx & 15;
        float s = 0.f;
#pragma unroll
        for (int d4 = 0; d4 < 16; d4++) {
            float4 qv = *(const float4*)(q + h * QKV_LD + d4 * 4);
            float4 kv = *(const float4*)(k + t * QKV_LD + d4 * 4);
            s += qv.x * kv.x + qv.y * kv.y + qv.z * kv.z + qv.w * kv.w;
        }
        sc[h * 17 + t] = s * 0.125f;
    }
    __syncwarp();

    if (lane < 16) {
        float mx = -1e30f;
#pragma unroll
        for (int t = 0; t < 16; t++) mx = fmaxf(mx, sc[lane * 17 + t]);
        float sum = 0.f;
#pragma unroll
        for (int t = 0; t < 16; t++) {
            float e = __expf(sc[lane * 17 + t] - mx);
            sum += e;
            sc[lane * 17 + t] = e;
        }
        const float inv = 1.f / sum;
#pragma unroll
        for (int t = 0; t < 16; t++) sc[lane * 17 + t] *= inv;
    }
    __syncwarp();

    float* dst = O + (size_t)m * 1024;
#pragma unroll
    for (int i = 0; i < 32; i++) {
        const int idx = i * 32 + lane;
        const int h = idx >> 6, d = idx & 63;
        float a0 = 0.f;
#pragma unroll
        for (int t = 0; t < 16; t++) a0 += sc[h * 17 + t] * v[t * QKV_LD + d];
        dst[idx] = __uint_as_float(f2tf32(a0));
    }
}

// ============================================================================
extern "C" void kernel_launch(void* const* d_in, const int* in_sizes, int n_in,
                              void* d_out, int out_size)
{
    (void)in_sizes; (void)n_in; (void)out_size;
    const float* x   = (const float*)d_in[0];
    const float* Wq  = (const float*)d_in[1];
    const float* Wk  = (const float*)d_in[2];
    const float* Wv  = (const float*)d_in[3];
    const float* Wfc = (const float*)d_in[4];
    float* out = (float*)d_out;

    float *Yp, *Op, *Xr, *Wp;
    cudaGetSymbolAddress((void**)&Yp, g_Y);
    cudaGetSymbolAddress((void**)&Op, g_O);
    cudaGetSymbolAddress((void**)&Xr, g_Xr);
    cudaGetSymbolAddress((void**)&Wp, g_W);

    cudaFuncSetAttribute(gemm_tf32_nt,
                         cudaFuncAttributeMaxDynamicSharedMemorySize, SMEM_TOTAL);

    // prologue: tf32 rounding
    round_tf32<<<16384, 256>>>((const float4*)x, (float4*)Xr, 4194304);
    round_w<<<4096, 256>>>((const float4*)Wq, (const float4*)Wk,
                           (const float4*)Wv, (const float4*)Wfc, (float4*)Wp);

    // GEMM1: Y = xr @ [Wq;Wk;Wv]^T   (tiles: 12 x 128)
    gemm_tf32_nt<<<dim3(12, 128), NTHREADS, SMEM_TOTAL>>>(Xr, Wp, Yp, 3072, 1024);
    // attention
    attn_kernel<<<8192, 64>>>(Yp, Op);
    // GEMM2: out = O @ Wfc^T         (tiles: 4 x 128)
    gemm_tf32_nt<<<dim3(4, 128), NTHREADS, SMEM_TOTAL>>>(Op, Wp + 3145728, out, 1024, 1024);
}

// round 4
// speedup vs baseline: 2.2706x; 2.2499x over previous
#include <cuda_runtime.h>
#include <cuda_fp16.h>
#include <cstdint>
#include <cstddef>

// ============================================================================
// MultiHeadAttention on GB300 — FP16 mma.sync path (same 11-bit mantissa as
// tf32, 2x rate, ldmatrix fragments, 3-stage cp.async pipeline)
//   conv : x, W -> fp16
//   GEMM1: Yh[16384,3072] = Xh @ Wqkv^T   (CTA 128x128, warp 64x32)
//   attn : per-token 16x16 head attention (fp32 math, fp16 I/O)
//   GEMM2: out(fp32) = Oh @ Wfc^T
// ============================================================================

#define NST 3
#define STAGE_B 16384          // 16KB per stage (A 8KB + B 8KB)
#define CTA_M 128
#define CTA_N 128
#define BK 32

__device__ __half g_Yh[50331648];   // 16384 x 3072
__device__ __half g_Oh[16777216];   // 16384 x 1024
__device__ __half g_Xh[16777216];   // x in fp16
__device__ __half g_Wh[4194304];    // Wq|Wk|Wv|Wfc in fp16

// ---------------------------------------------------------------- helpers
__device__ __forceinline__ uint32_t smem_u32(const void* p) {
    uint32_t a;
    asm("{ .reg .u64 t; cvta.to.shared.u64 t, %1; cvt.u32.u64 %0, t; }"
        : "=r"(a) : "l"(p));
    return a;
}
__device__ __forceinline__ void cp16(uint32_t saddr, const void* gptr) {
    asm volatile("cp.async.cg.shared.global [%0], [%1], 16;\n" :: "r"(saddr), "l"(gptr));
}
__device__ __forceinline__ void cp_commit() { asm volatile("cp.async.commit_group;\n"); }
template <int N>
__device__ __forceinline__ void cp_wait() {
    asm volatile("cp.async.wait_group %0;\n" :: "n"(N));
}
__device__ __forceinline__ void ldsm4(uint32_t& r0, uint32_t& r1, uint32_t& r2,
                                      uint32_t& r3, uint32_t addr) {
    asm volatile("ldmatrix.sync.aligned.m8n8.x4.shared.b16 {%0,%1,%2,%3}, [%4];"
                 : "=r"(r0), "=r"(r1), "=r"(r2), "=r"(r3) : "r"(addr));
}
__device__ __forceinline__ void mma_f16(float c[4], const uint32_t a[4], const uint32_t b[2]) {
    asm volatile(
        "mma.sync.aligned.m16n8k16.row.col.f32.f16.f16.f32 "
        "{%0,%1,%2,%3}, {%4,%5,%6,%7}, {%8,%9}, {%0,%1,%2,%3};\n"
        : "+f"(c[0]), "+f"(c[1]), "+f"(c[2]), "+f"(c[3])
        : "r"(a[0]), "r"(a[1]), "r"(a[2]), "r"(a[3]), "r"(b[0]), "r"(b[1]));
}

// ============================================================================
// FP16 NT GEMM: C[128x128 tile] = A[M,K] @ B[N,K]^T
// smem row = 64B (32 halves), swizzle: 16B-group g' = g ^ ((row>>1)&3)
// ============================================================================
template <bool OUT_HALF>
__global__ void __launch_bounds__(256, 2)
gemm_f16_nt(const __half* __restrict__ A, const __half* __restrict__ B,
            void* __restrict__ Cout, int ldc, int K)
{
    __shared__ __align__(128) char smem[NST * STAGE_B];
    const uint32_t sb = smem_u32(smem);

    const int tid  = threadIdx.x;
    const int lane = tid & 31;
    const int wid  = tid >> 5;
    const int warp_m = wid & 1;     // 64 rows
    const int warp_n = wid >> 1;    // 32 cols

    const int mtile = blockIdx.y, ntile = blockIdx.x;
    const __half* Ab = A + (size_t)(mtile * CTA_M) * K;
    const __half* Bb = B + (size_t)(ntile * CTA_N) * K;

    // -------- loader setup: 4x cp16 per thread per k-tile
    const __half* gsrc[4];
    uint32_t soff[4];
#pragma unroll
    for (int i = 0; i < 4; i++) {
        const int id = tid + i * 256;       // 0..1023
        const int op = id >> 9;             // 0=A 1=B
        const int rr = (id >> 2) & 127;
        const int g  = id & 3;
        gsrc[i] = (op ? Bb : Ab) + (size_t)rr * K + g * 8;
        soff[i] = (uint32_t)(op * 8192 + rr * 64 + ((g ^ ((rr >> 1) & 3)) << 4));
    }

    // -------- fragment ldmatrix addresses (stage 0, ks=0)
    const int ch = lane >> 4;               // 16B-chunk within k16
    uint32_t a_addr[4], b_addr[2];
    {
        const int ar = warp_m * 64 + (lane & 15);
#pragma unroll
        for (int mt = 0; mt < 4; mt++) {
            const int r = ar + mt * 16;
            a_addr[mt] = sb + r * 64 + ((ch ^ ((r >> 1) & 3)) << 4);
        }
        const int br = warp_n * 32 + (lane & 15);
#pragma unroll
        for (int p = 0; p < 2; p++) {
            const int r = br + p * 16;
            b_addr[p] = sb + 8192 + r * 64 + ((ch ^ ((r >> 1) & 3)) << 4);
        }
    }

    float acc[4][4][4];
#pragma unroll
    for (int mt = 0; mt < 4; mt++)
#pragma unroll
        for (int nt = 0; nt < 4; nt++)
#pragma unroll
            for (int i = 0; i < 4; i++) acc[mt][nt][i] = 0.f;

    const int NKT = K >> 5;   // K/32

    // prefill NST-1 stages
#pragma unroll
    for (int s = 0; s < NST - 1; s++) {
#pragma unroll
        for (int i = 0; i < 4; i++) cp16(sb + s * STAGE_B + soff[i], gsrc[i] + s * 32);
        cp_commit();
    }

    for (int kt = 0; kt < NKT; kt++) {
        cp_wait<NST - 2>();
        __syncthreads();

        const int nk = kt + NST - 1;
        if (nk < NKT) {
            const uint32_t so = (uint32_t)(nk % NST) * STAGE_B;
#pragma unroll
            for (int i = 0; i < 4; i++) cp16(sb + so + soff[i], gsrc[i] + nk * 32);
            cp_commit();
        } else {
            cp_commit();    // keep group count in sync with waits
        }

        const uint32_t so = (uint32_t)(kt % NST) * STAGE_B;

#pragma unroll
        for (int ks = 0; ks < 2; ks++) {
            const uint32_t kx = (uint32_t)ks << 5;   // flips 16B-group bit1
            uint32_t a[4][4], b[4][2];
#pragma unroll
            for (int mt = 0; mt < 4; mt++)
                ldsm4(a[mt][0], a[mt][1], a[mt][2], a[mt][3],
                      (a_addr[mt] + so) ^ kx);
#pragma unroll
            for (int p = 0; p < 2; p++) {
                uint32_t t0, t1, t2, t3;
                ldsm4(t0, t1, t2, t3, (b_addr[p] + so) ^ kx);
                b[2 * p][0] = t0; b[2 * p][1] = t2;
                b[2 * p + 1][0] = t1; b[2 * p + 1][1] = t3;
            }
#pragma unroll
            for (int mt = 0; mt < 4; mt++)
#pragma unroll
                for (int nt = 0; nt < 4; nt++)
                    mma_f16(acc[mt][nt], a[mt], b[nt]);
        }
    }

    // -------- epilogue
    const int r_in = (lane >> 2);
    const int c_in = 2 * (lane & 3);
    if (OUT_HALF) {
        __half* Cb = (__half*)Cout + (size_t)(mtile * CTA_M) * ldc
                   + (size_t)ntile * CTA_N;
#pragma unroll
        for (int mt = 0; mt < 4; mt++)
#pragma unroll
            for (int nt = 0; nt < 4; nt++) {
                const int r0 = warp_m * 64 + mt * 16 + r_in;
                const int c0 = warp_n * 32 + nt * 8 + c_in;
                *(__half2*)(Cb + (size_t)r0 * ldc + c0) =
                    __floats2half2_rn(acc[mt][nt][0], acc[mt][nt][1]);
                *(__half2*)(Cb + (size_t)(r0 + 8) * ldc + c0) =
                    __floats2half2_rn(acc[mt][nt][2], acc[mt][nt][3]);
            }
    } else {
        float* Cb = (float*)Cout + (size_t)(mtile * CTA_M) * ldc
                  + (size_t)ntile * CTA_N;
#pragma unroll
        for (int mt = 0; mt < 4; mt++)
#pragma unroll
            for (int nt = 0; nt < 4; nt++) {
                const int r0 = warp_m * 64 + mt * 16 + r_in;
                const int c0 = warp_n * 32 + nt * 8 + c_in;
                *(float2*)(Cb + (size_t)r0 * ldc + c0) =
                    make_float2(acc[mt][nt][0], acc[mt][nt][1]);
                *(float2*)(Cb + (size_t)(r0 + 8) * ldc + c0) =
                    make_float2(acc[mt][nt][2], acc[mt][nt][3]);
            }
    }
}

// ============================================================================
// fp32 -> fp16 converters
// ============================================================================
__global__ void __launch_bounds__(256)
f2h_x(const float4* __restrict__ src, uint2* __restrict__ dst, int n4)
{
    int i = blockIdx.x * 256 + threadIdx.x;
    if (i < n4) {
        float4 v = src[i];
        __half2 h0 = __floats2half2_rn(v.x, v.y);
        __half2 h1 = __floats2half2_rn(v.z, v.w);
        uint2 o;
        o.x = *(uint32_t*)&h0;
        o.y = *(uint32_t*)&h1;
        dst[i] = o;
    }
}

__global__ void __launch_bounds__(256)
f2h_w(const float4* __restrict__ w0, const float4* __restrict__ w1,
      const float4* __restrict__ w2, const float4* __restrict__ w3,
      uint2* __restrict__ dst)
{
    int bx = blockIdx.x;                  // 0..4095
    int m  = bx >> 10;
    int i  = (bx & 1023) * 256 + threadIdx.x;   // 0..262143
    const float4* src = (m == 0) ? w0 : (m == 1) ? w1 : (m == 2) ? w2 : w3;
    float4 v = src[i];
    __half2 h0 = __floats2half2_rn(v.x, v.y);
    __half2 h1 = __floats2half2_rn(v.z, v.w);
    uint2 o;
    o.x = *(uint32_t*)&h0;
    o.y = *(uint32_t*)&h1;
    dst[(size_t)m * 262144 + i] = o;
}

// ============================================================================
// Per-token head-axis attention, fp16 I/O, fp32 math.
// ============================================================================
#define QKV_LD 68
__global__ void __launch_bounds__(64)
attn_kernel(const __half* __restrict__ Y, __half* __restrict__ O)
{
    __shared__ float sm[2][3 * 16 * QKV_LD + 16 * 17];

    const int lane = threadIdx.x & 31;
    const int w    = threadIdx.x >> 5;
    const int m    = blockIdx.x * 2 + w;

    float* q  = &sm[w][0];
    float* k  = q + 16 * QKV_LD;
    float* v  = k + 16 * QKV_LD;
    float* sc = v + 16 * QKV_LD;

    const uint4* src = (const uint4*)(Y + (size_t)m * 3072);   // 384 uint4

#pragma unroll
    for (int it = 0; it < 12; it++) {
        const int f = it * 32 + lane;              // 0..383
        uint4 raw = src[f];
        const int sec  = f >> 7;                   // 0=Q 1=K 2=V
        const int wi   = f & 127;
        const int row  = wi >> 3;                  // 8 uint4 per 64-half row
        const int col8 = wi & 7;
        float* dst = (sec == 0) ? q : (sec == 1 ? k : v);
        const __half2* hp = (const __half2*)&raw;
        float2 f0 = __half22float2(hp[0]);
        float2 f1 = __half22float2(hp[1]);
        float2 f2 = __half22float2(hp[2]);
        float2 f3 = __half22float2(hp[3]);
        float* d = dst + row * QKV_LD + col8 * 8;
        *(float4*)(d)     = make_float4(f0.x, f0.y, f1.x, f1.y);
        *(float4*)(d + 4) = make_float4(f2.x, f2.y, f3.x, f3.y);
    }
    __syncwarp();

#pragma unroll
    for (int p = 0; p < 8; p++) {
        const int idx = p * 32 + lane;
        const int h = idx >> 4, t = idx & 15;
        float s = 0.f;
#pragma unroll
        for (int d4 = 0; d4 < 16; d4++) {
            float4 qv = *(const float4*)(q + h * QKV_LD + d4 * 4);
            float4 kv = *(const float4*)(k + t * QKV_LD + d4 * 4);
            s += qv.x * kv.x + qv.y * kv.y + qv.z * kv.z + qv.w * kv.w;
        }
        sc[h * 17 + t] = s * 0.125f;
    }
    __syncwarp();

    if (lane < 16) {
        float mx = -1e30f;
#pragma unroll
        for (int t = 0; t < 16; t++) mx = fmaxf(mx, sc[lane * 17 + t]);
        float sum = 0.f;
#pragma unroll
        for (int t = 0; t < 16; t++) {
            float e = __expf(sc[lane * 17 + t] - mx);
            sum += e;
            sc[lane * 17 + t] = e;
        }
        const float inv = 1.f / sum;
#pragma unroll
        for (int t = 0; t < 16; t++) sc[lane * 17 + t] *= inv;
    }
    __syncwarp();

    __half* dst = O + (size_t)m * 1024;
#pragma unroll
    for (int i = 0; i < 16; i++) {     // head h = i, lanes cover d = 2*lane, 2*lane+1
        const int d = lane * 2;
        float a0 = 0.f, a1 = 0.f;
#pragma unroll
        for (int t = 0; t < 16; t++) {
            const float s = sc[i * 17 + t];
            a0 += s * v[t * QKV_LD + d];
            a1 += s * v[t * QKV_LD + d + 1];
        }
        *(__half2*)(dst + i * 64 + d) = __floats2half2_rn(a0, a1);
    }
}

// ============================================================================
extern "C" void kernel_launch(void* const* d_in, const int* in_sizes, int n_in,
                              void* d_out, int out_size)
{
    (void)in_sizes; (void)n_in; (void)out_size;
    const float* x   = (const float*)d_in[0];
    const float* Wq  = (const float*)d_in[1];
    const float* Wk  = (const float*)d_in[2];
    const float* Wv  = (const float*)d_in[3];
    const float* Wfc = (const float*)d_in[4];
    float* out = (float*)d_out;

    __half *Yh, *Oh, *Xh, *Wh;
    cudaGetSymbolAddress((void**)&Yh, g_Yh);
    cudaGetSymbolAddress((void**)&Oh, g_Oh);
    cudaGetSymbolAddress((void**)&Xh, g_Xh);
    cudaGetSymbolAddress((void**)&Wh, g_Wh);

    // fp16 conversion
    f2h_x<<<16384, 256>>>((const float4*)x, (uint2*)Xh, 4194304);
    f2h_w<<<4096, 256>>>((const float4*)Wq, (const float4*)Wk,
                         (const float4*)Wv, (const float4*)Wfc, (uint2*)Wh);

    // GEMM1: Yh = Xh @ [Wq;Wk;Wv]^T
    gemm_f16_nt<true><<<dim3(24, 128), 256>>>(Xh, Wh, Yh, 3072, 1024);
    // attention
    attn_kernel<<<8192, 64>>>(Yh, Oh);
    // GEMM2: out = Oh @ Wfc^T  (fp32 out)
    gemm_f16_nt<false><<<dim3(8, 128), 256>>>(Oh, Wh + 3145728, out, 1024, 1024);
}